// round 4
// baseline (speedup 1.0000x reference)
#include <cuda_runtime.h>
#include <cuda_bf16.h>

// C[i, j] = sum_k |boxes[i,k] - tpts[j,k]|  -  sigmoid(logits[i, labels[j]])
// NR = bs*Q = 8192 rows, NC = bs*T = 4096 cols. Output row-major fp32 (128 MB).
//
// HBM-writeback-bound. Design:
//  - Block = 1024 threads = one full output row (4096 cols): each thread owns
//    one float4 target group (register-cached once). Each row iteration is one
//    contiguous 16 KB store burst per block -> best DRAM page locality.
//  - Grid = 304 = 2 blocks x 152 SMs: exactly one wave at full occupancy.
//    Each block owns a contiguous chunk of ~27 rows.
//  - Row data (box float4 + negated sigmoid float2) staged in smem once per
//    block; hot loop reads broadcast LDS only. Single __syncthreads.

#define TPB 1024
#define NBLK 304          // 2 blocks per SM x 152 SMs (GB300)
#define MAXR 96           // max rows per block chunk (8192/304 = 27)

__device__ __forceinline__ float l1_4(float4 p, float4 t) {
    return fabsf(p.x - t.x) + fabsf(p.y - t.y)
         + fabsf(p.z - t.z) + fabsf(p.w - t.w);
}

__global__ __launch_bounds__(TPB, 2) void cost_kernel(
    const float* __restrict__ logits,  // [NR, 2]
    const float* __restrict__ boxes,   // [NR, 4]
    const float* __restrict__ tpts,    // [NC, 4]
    const int*   __restrict__ tlab,    // [NC]
    float*       __restrict__ out,     // [NR, NC]
    int NR, int NC)
{
    __shared__ float4 s_box[MAXR];
    __shared__ float2 s_np[MAXR];

    // Contiguous row chunk for this block.
    const int base = NR / NBLK;
    const int rem  = NR % NBLK;
    const int b    = blockIdx.x;
    const int i0   = b * base + min(b, rem);
    const int nr   = base + (b < rem ? 1 : 0);

    // Stage row data: box + negated sigmoid probs.
    for (int r = threadIdx.x; r < nr; r += TPB) {
        const int i = i0 + r;
        s_box[r] = reinterpret_cast<const float4*>(boxes)[i];
        float2 lg = reinterpret_cast<const float2*>(logits)[i];
        float2 np;
        np.x = -1.0f / (1.0f + __expf(-lg.x));
        np.y = -1.0f / (1.0f + __expf(-lg.y));
        s_np[r] = np;
    }

    const int NC4 = NC >> 2;
    const int g   = threadIdx.x;          // this thread's float4 column group
    const bool haveG = (g < NC4);

    // Register-cached target (one float4 group + label selects per thread).
    float4 t0 = make_float4(0.f, 0.f, 0.f, 0.f);
    float4 t1 = t0, t2 = t0, t3 = t0;
    bool s0 = false, s1 = false, s2 = false, s3 = false;
    if (haveG) {
        const float4* tpts4 = reinterpret_cast<const float4*>(tpts);
        t0 = tpts4[4 * g + 0];
        t1 = tpts4[4 * g + 1];
        t2 = tpts4[4 * g + 2];
        t3 = tpts4[4 * g + 3];
        s0 = tlab[4 * g + 0] != 0;
        s1 = tlab[4 * g + 1] != 0;
        s2 = tlab[4 * g + 2] != 0;
        s3 = tlab[4 * g + 3] != 0;
    }

    __syncthreads();

    if (!haveG) return;

    #pragma unroll 2
    for (int r = 0; r < nr; ++r) {
        const int i = i0 + r;
        const float4 p  = s_box[r];    // broadcast LDS, conflict-free
        const float2 np = s_np[r];

        float4 o;
        o.x = l1_4(p, t0) + (s0 ? np.y : np.x);
        o.y = l1_4(p, t1) + (s1 ? np.y : np.x);
        o.z = l1_4(p, t2) + (s2 ? np.y : np.x);
        o.w = l1_4(p, t3) + (s3 ? np.y : np.x);

        __stcs(reinterpret_cast<float4*>(out) + (size_t)i * NC4 + g, o);
    }
}

// Fallback for NC wider than TPB*4 columns (not hit for this shape):
__global__ __launch_bounds__(TPB, 2) void cost_kernel_generic(
    const float* __restrict__ logits,
    const float* __restrict__ boxes,
    const float* __restrict__ tpts,
    const int*   __restrict__ tlab,
    float*       __restrict__ out,
    int NR, int NC)
{
    const int NC4 = NC >> 2;
    const int base = NR / NBLK;
    const int rem  = NR % NBLK;
    const int b    = blockIdx.x;
    const int i0   = b * base + min(b, rem);
    const int nr   = base + (b < rem ? 1 : 0);
    const float4* tpts4 = reinterpret_cast<const float4*>(tpts);

    for (int r = 0; r < nr; ++r) {
        const int i = i0 + r;
        const float4 p  = reinterpret_cast<const float4*>(boxes)[i];
        const float2 lg = reinterpret_cast<const float2*>(logits)[i];
        const float p0 = -1.0f / (1.0f + __expf(-lg.x));
        const float p1 = -1.0f / (1.0f + __expf(-lg.y));
        for (int g = threadIdx.x; g < NC4; g += TPB) {
            float4 o;
            float4 t = tpts4[4 * g + 0];
            o.x = l1_4(p, t) + (tlab[4 * g + 0] ? p1 : p0);
            t = tpts4[4 * g + 1];
            o.y = l1_4(p, t) + (tlab[4 * g + 1] ? p1 : p0);
            t = tpts4[4 * g + 2];
            o.z = l1_4(p, t) + (tlab[4 * g + 2] ? p1 : p0);
            t = tpts4[4 * g + 3];
            o.w = l1_4(p, t) + (tlab[4 * g + 3] ? p1 : p0);
            __stcs(reinterpret_cast<float4*>(out) + (size_t)i * NC4 + g, o);
        }
    }
}

extern "C" void kernel_launch(void* const* d_in, const int* in_sizes, int n_in,
                              void* d_out, int out_size)
{
    // Inputs (metadata order):
    //   0: pred_logits  [bs, Q, 2]      float32
    //   1: pred_boxes   [bs, Q, 4]      float32
    //   2: tgt_pts      [bs, T, 2, 2]   float32
    //   3: tgt_labels   [bs, T]         int32
    const float* logits = (const float*)d_in[0];
    const float* boxes  = (const float*)d_in[1];
    const float* tpts   = (const float*)d_in[2];
    const int*   tlab   = (const int*)d_in[3];
    float* out = (float*)d_out;

    const int NR = in_sizes[1] / 4;   // bs*Q
    const int NC = in_sizes[3];       // bs*T

    if ((NC >> 2) <= TPB && NR >= NBLK) {
        cost_kernel<<<NBLK, TPB>>>(logits, boxes, tpts, tlab, out, NR, NC);
    } else {
        cost_kernel_generic<<<NBLK, TPB>>>(logits, boxes, tpts, tlab, out, NR, NC);
    }
}

// round 5
// speedup vs baseline: 1.0113x; 1.0113x over previous
#include <cuda_runtime.h>
#include <cuda_bf16.h>

// C[i, j] = sum_k |boxes[i,k] - tpts[j,k]|  -  sigmoid(logits[i, labels[j]])
// NR = bs*Q = 8192 rows, NC = bs*T = 4096 cols. Output row-major fp32 (128 MB).
//
// Kernel is at the DRAM-write ceiling (~5.6 TB/s for a pure fp32 store
// stream). R5 change: write-through stores (__stwt) so the 128 MB output
// never accumulates as dirty L2 that must drain into the next graph replay.
// Geometry = R3 (best measured total): block 128 thr covers 1024 cols x 32
// rows; row data (box + negated sigmoid) staged in smem, broadcast LDS in
// the hot loop; targets register-cached (2 float4 groups / thread).

#define RPB 32          // rows per block
#define TPB 128         // threads per block; block covers 128*8 = 1024 columns

__device__ __forceinline__ float l1_4(float4 p, float4 t) {
    return fabsf(p.x - t.x) + fabsf(p.y - t.y)
         + fabsf(p.z - t.z) + fabsf(p.w - t.w);
}

__global__ __launch_bounds__(TPB) void cost_kernel(
    const float* __restrict__ logits,  // [NR, 2]
    const float* __restrict__ boxes,   // [NR, 4]
    const float* __restrict__ tpts,    // [NC, 4]
    const int*   __restrict__ tlab,    // [NC]
    float*       __restrict__ out,     // [NR, NC]
    int NR, int NC)
{
    __shared__ float4 s_box[RPB];
    __shared__ float2 s_np[RPB];

    const int NC4 = NC >> 2;
    const int gA  = blockIdx.x * (2 * TPB) + threadIdx.x;   // float4 group A
    const int gB  = gA + TPB;                                // float4 group B
    const int i0  = blockIdx.y * RPB;

    // Stage row data: first 32 threads each handle one row.
    if (threadIdx.x < RPB) {
        int i = i0 + threadIdx.x;
        if (i < NR) {
            s_box[threadIdx.x] = reinterpret_cast<const float4*>(boxes)[i];
            float2 lg = reinterpret_cast<const float2*>(logits)[i];
            float2 np;
            np.x = -1.0f / (1.0f + __expf(-lg.x));
            np.y = -1.0f / (1.0f + __expf(-lg.y));
            s_np[threadIdx.x] = np;
        }
    }

    const float4* tpts4 = reinterpret_cast<const float4*>(tpts);

    // Register-cached targets: 8 columns per thread.
    float4 a0, a1, a2, a3, b0, b1, b2, b3;
    bool sa0 = false, sa1 = false, sa2 = false, sa3 = false;
    bool sb0 = false, sb1 = false, sb2 = false, sb3 = false;
    const bool haveA = (4 * gA + 3 < NC);
    const bool haveB = (4 * gB + 3 < NC);
    if (haveA) {
        a0 = tpts4[4 * gA + 0];  a1 = tpts4[4 * gA + 1];
        a2 = tpts4[4 * gA + 2];  a3 = tpts4[4 * gA + 3];
        sa0 = tlab[4 * gA + 0] != 0;  sa1 = tlab[4 * gA + 1] != 0;
        sa2 = tlab[4 * gA + 2] != 0;  sa3 = tlab[4 * gA + 3] != 0;
    }
    if (haveB) {
        b0 = tpts4[4 * gB + 0];  b1 = tpts4[4 * gB + 1];
        b2 = tpts4[4 * gB + 2];  b3 = tpts4[4 * gB + 3];
        sb0 = tlab[4 * gB + 0] != 0;  sb1 = tlab[4 * gB + 1] != 0;
        sb2 = tlab[4 * gB + 2] != 0;  sb3 = tlab[4 * gB + 3] != 0;
    }

    __syncthreads();

    if (!haveA) return;

    const int rmax = min(RPB, NR - i0);

    #pragma unroll 4
    for (int r = 0; r < rmax; ++r) {
        const int i = i0 + r;
        const float4 p  = s_box[r];   // broadcast LDS, conflict-free
        const float2 np = s_np[r];

        float4 oA;
        oA.x = l1_4(p, a0) + (sa0 ? np.y : np.x);
        oA.y = l1_4(p, a1) + (sa1 ? np.y : np.x);
        oA.z = l1_4(p, a2) + (sa2 ? np.y : np.x);
        oA.w = l1_4(p, a3) + (sa3 ? np.y : np.x);

        float4* orow = reinterpret_cast<float4*>(out) + (size_t)i * NC4;
        __stwt(orow + gA, oA);        // write-through: no dirty-L2 buildup

        if (haveB) {
            float4 oB;
            oB.x = l1_4(p, b0) + (sb0 ? np.y : np.x);
            oB.y = l1_4(p, b1) + (sb1 ? np.y : np.x);
            oB.z = l1_4(p, b2) + (sb2 ? np.y : np.x);
            oB.w = l1_4(p, b3) + (sb3 ? np.y : np.x);
            __stwt(orow + gB, oB);
        }
    }
}

extern "C" void kernel_launch(void* const* d_in, const int* in_sizes, int n_in,
                              void* d_out, int out_size)
{
    // Inputs (metadata order):
    //   0: pred_logits  [bs, Q, 2]      float32
    //   1: pred_boxes   [bs, Q, 4]      float32
    //   2: tgt_pts      [bs, T, 2, 2]   float32
    //   3: tgt_labels   [bs, T]         int32
    const float* logits = (const float*)d_in[0];
    const float* boxes  = (const float*)d_in[1];
    const float* tpts   = (const float*)d_in[2];
    const int*   tlab   = (const int*)d_in[3];
    float* out = (float*)d_out;

    const int NR = in_sizes[1] / 4;   // bs*Q
    const int NC = in_sizes[3];       // bs*T

    const int cols_per_block = 2 * TPB * 4;   // 1024 columns
    dim3 grid((NC + cols_per_block - 1) / cols_per_block,
              (NR + RPB - 1) / RPB);
    cost_kernel<<<grid, TPB>>>(logits, boxes, tpts, tlab, out, NR, NC);
}

// round 6
// speedup vs baseline: 1.0503x; 1.0386x over previous
#include <cuda_runtime.h>
#include <cuda_bf16.h>

// C[i, j] = sum_k |boxes[i,k] - tpts[j,k]|  -  sigmoid(logits[i, labels[j]])
// NR = bs*Q = 8192 rows, NC = bs*T = 4096 cols. Output row-major fp32 (128 MB).
//
// FINAL: kernel is at the steady-state HBM write floor. 128 MB of fp32 output
// is mandatory; measured effective store throughput ~5.6 TB/s in-kernel and
// ~5 TB/s replay-period steady state. Duration proven invariant to occupancy
// (38% vs 78%), block geometry (128x(1024c,32r) vs 1024x(4096c,27r)) and
// store policy (default / __stcs / __stwt). This is the best measured
// configuration (R3): block 128 thr covers 1024 cols x 32 rows; row data
// (box float4 + negated sigmoid float2) staged in 768 B smem, broadcast LDS
// in the hot loop; targets register-cached (2 float4 groups / thread);
// evict-first streaming stores.

#define RPB 32          // rows per block
#define TPB 128         // threads per block; block covers 128*8 = 1024 columns

__device__ __forceinline__ float l1_4(float4 p, float4 t) {
    return fabsf(p.x - t.x) + fabsf(p.y - t.y)
         + fabsf(p.z - t.z) + fabsf(p.w - t.w);
}

__global__ __launch_bounds__(TPB) void cost_kernel(
    const float* __restrict__ logits,  // [NR, 2]
    const float* __restrict__ boxes,   // [NR, 4]
    const float* __restrict__ tpts,    // [NC, 4]
    const int*   __restrict__ tlab,    // [NC]
    float*       __restrict__ out,     // [NR, NC]
    int NR, int NC)
{
    __shared__ float4 s_box[RPB];
    __shared__ float2 s_np[RPB];

    const int NC4 = NC >> 2;
    const int gA  = blockIdx.x * (2 * TPB) + threadIdx.x;   // float4 group A
    const int gB  = gA + TPB;                                // float4 group B
    const int i0  = blockIdx.y * RPB;

    // Stage row data: first 32 threads each handle one row.
    if (threadIdx.x < RPB) {
        int i = i0 + threadIdx.x;
        if (i < NR) {
            s_box[threadIdx.x] = reinterpret_cast<const float4*>(boxes)[i];
            float2 lg = reinterpret_cast<const float2*>(logits)[i];
            float2 np;
            np.x = -1.0f / (1.0f + __expf(-lg.x));
            np.y = -1.0f / (1.0f + __expf(-lg.y));
            s_np[threadIdx.x] = np;
        }
    }

    const float4* tpts4 = reinterpret_cast<const float4*>(tpts);

    // Register-cached targets: 8 columns per thread.
    float4 a0, a1, a2, a3, b0, b1, b2, b3;
    bool sa0 = false, sa1 = false, sa2 = false, sa3 = false;
    bool sb0 = false, sb1 = false, sb2 = false, sb3 = false;
    const bool haveA = (4 * gA + 3 < NC);
    const bool haveB = (4 * gB + 3 < NC);
    if (haveA) {
        a0 = tpts4[4 * gA + 0];  a1 = tpts4[4 * gA + 1];
        a2 = tpts4[4 * gA + 2];  a3 = tpts4[4 * gA + 3];
        sa0 = tlab[4 * gA + 0] != 0;  sa1 = tlab[4 * gA + 1] != 0;
        sa2 = tlab[4 * gA + 2] != 0;  sa3 = tlab[4 * gA + 3] != 0;
    }
    if (haveB) {
        b0 = tpts4[4 * gB + 0];  b1 = tpts4[4 * gB + 1];
        b2 = tpts4[4 * gB + 2];  b3 = tpts4[4 * gB + 3];
        sb0 = tlab[4 * gB + 0] != 0;  sb1 = tlab[4 * gB + 1] != 0;
        sb2 = tlab[4 * gB + 2] != 0;  sb3 = tlab[4 * gB + 3] != 0;
    }

    __syncthreads();

    if (!haveA) return;

    const int rmax = min(RPB, NR - i0);

    #pragma unroll 4
    for (int r = 0; r < rmax; ++r) {
        const int i = i0 + r;
        const float4 p  = s_box[r];   // broadcast LDS, conflict-free
        const float2 np = s_np[r];

        float4 oA;
        oA.x = l1_4(p, a0) + (sa0 ? np.y : np.x);
        oA.y = l1_4(p, a1) + (sa1 ? np.y : np.x);
        oA.z = l1_4(p, a2) + (sa2 ? np.y : np.x);
        oA.w = l1_4(p, a3) + (sa3 ? np.y : np.x);

        float4* orow = reinterpret_cast<float4*>(out) + (size_t)i * NC4;
        __stcs(orow + gA, oA);

        if (haveB) {
            float4 oB;
            oB.x = l1_4(p, b0) + (sb0 ? np.y : np.x);
            oB.y = l1_4(p, b1) + (sb1 ? np.y : np.x);
            oB.z = l1_4(p, b2) + (sb2 ? np.y : np.x);
            oB.w = l1_4(p, b3) + (sb3 ? np.y : np.x);
            __stcs(orow + gB, oB);
        }
    }
}

extern "C" void kernel_launch(void* const* d_in, const int* in_sizes, int n_in,
                              void* d_out, int out_size)
{
    // Inputs (metadata order):
    //   0: pred_logits  [bs, Q, 2]      float32
    //   1: pred_boxes   [bs, Q, 4]      float32
    //   2: tgt_pts      [bs, T, 2, 2]   float32
    //   3: tgt_labels   [bs, T]         int32
    const float* logits = (const float*)d_in[0];
    const float* boxes  = (const float*)d_in[1];
    const float* tpts   = (const float*)d_in[2];
    const int*   tlab   = (const int*)d_in[3];
    float* out = (float*)d_out;

    const int NR = in_sizes[1] / 4;   // bs*Q
    const int NC = in_sizes[3];       // bs*T

    const int cols_per_block = 2 * TPB * 4;   // 1024 columns
    dim3 grid((NC + cols_per_block - 1) / cols_per_block,
              (NR + RPB - 1) / RPB);
    cost_kernel<<<grid, TPB>>>(logits, boxes, tpts, tlab, out, NR, NC);
}